// round 2
// baseline (speedup 1.0000x reference)
#include <cuda_runtime.h>
#include <math.h>

#define B_  8
#define T_  2048
#define C_  2048
#define HS_ 64
#define H_  32
#define M_  (B_*T_)   // 16384

// 8 buffers of M_*C_ floats = 1 GiB static scratch (allowed: __device__ global)
__device__ float g_scratch[(size_t)8 * (size_t)M_ * (size_t)C_];

// ---------------------------------------------------------------------------
// Token-shift mixing: xk/xv/xr/xg = xx + tm*(x - xx), xx = x shifted by 1 token
// ---------------------------------------------------------------------------
__global__ __launch_bounds__(256) void mix_kernel(
    const float* __restrict__ x,
    const float* __restrict__ tmk, const float* __restrict__ tmv,
    const float* __restrict__ tmr, const float* __restrict__ tmg,
    float* __restrict__ xk, float* __restrict__ xv,
    float* __restrict__ xr, float* __restrict__ xg)
{
    size_t idx4 = (size_t)blockIdx.x * blockDim.x + threadIdx.x; // over M_*C_/4
    size_t idx  = idx4 * 4;
    int    c    = (int)(idx % C_);
    size_t m    = idx / C_;
    int    t    = (int)(m % T_);

    float4 xc = *(const float4*)(x + idx);
    float4 xp = make_float4(0.f, 0.f, 0.f, 0.f);
    if (t != 0) xp = *(const float4*)(x + idx - C_);

    float4 o;
#define DO_MIX(TM, DST)                                                     \
    {                                                                       \
        float4 w4 = *(const float4*)((TM) + c);                             \
        o.x = fmaf(w4.x, xc.x - xp.x, xp.x);                                \
        o.y = fmaf(w4.y, xc.y - xp.y, xp.y);                                \
        o.z = fmaf(w4.z, xc.z - xp.z, xp.z);                                \
        o.w = fmaf(w4.w, xc.w - xp.w, xp.w);                                \
        *(float4*)((DST) + idx) = o;                                        \
    }
    DO_MIX(tmk, xk)
    DO_MIX(tmv, xv)
    DO_MIX(tmr, xr)
    DO_MIX(tmg, xg)
#undef DO_MIX
}

// ---------------------------------------------------------------------------
// fp32 SGEMM: C[M,N] = A[M,K] @ B[K,N], M=16384, N=K=2048 hardcoded.
// 128x128 block tile, BK=16, 256 threads, 8x8 register tile.
// epi==1: silu epilogue (for the gate projection).
// ---------------------------------------------------------------------------
__global__ __launch_bounds__(256) void sgemm_kernel(
    const float* __restrict__ A, const float* __restrict__ Bm,
    float* __restrict__ Cm, int epi)
{
    __shared__ float As[16][132];   // padded to kill STS bank conflicts
    __shared__ float Bs[16][132];

    const int tid = threadIdx.x;
    const int tr  = tid >> 4;   // 0..15
    const int tc  = tid & 15;   // 0..15

    const float* Ag = A  + (size_t)blockIdx.y * 128 * 2048;
    const float* Bg = Bm + (size_t)blockIdx.x * 128;

    float acc[8][8];
#pragma unroll
    for (int i = 0; i < 8; i++)
#pragma unroll
        for (int j = 0; j < 8; j++) acc[i][j] = 0.f;

    for (int k0 = 0; k0 < 2048; k0 += 16) {
#pragma unroll
        for (int u = 0; u < 2; u++) {
            int lin = tid + 256 * u;           // 0..511
            // A tile 128x16 -> transposed store
            int arow = lin >> 2;               // 0..127
            int acol = (lin & 3) << 2;         // 0,4,8,12
            float4 va = *(const float4*)(Ag + (size_t)arow * 2048 + k0 + acol);
            As[acol + 0][arow] = va.x;
            As[acol + 1][arow] = va.y;
            As[acol + 2][arow] = va.z;
            As[acol + 3][arow] = va.w;
            // B tile 16x128 -> direct store
            int brow = lin >> 5;               // 0..15
            int bcol = (lin & 31) << 2;        // 0..124
            float4 vb = *(const float4*)(Bg + (size_t)(k0 + brow) * 2048 + bcol);
            *(float4*)(&Bs[brow][bcol]) = vb;
        }
        __syncthreads();

#pragma unroll
        for (int kk = 0; kk < 16; kk++) {
            float a[8], b[8];
#pragma unroll
            for (int i = 0; i < 8; i++) a[i] = As[kk][tr * 8 + i];
#pragma unroll
            for (int j = 0; j < 8; j++) b[j] = Bs[kk][tc * 8 + j];
#pragma unroll
            for (int i = 0; i < 8; i++)
#pragma unroll
                for (int j = 0; j < 8; j++)
                    acc[i][j] = fmaf(a[i], b[j], acc[i][j]);
        }
        __syncthreads();
    }

#pragma unroll
    for (int i = 0; i < 8; i++) {
        size_t row = (size_t)blockIdx.y * 128 + tr * 8 + i;
        float* cp = Cm + row * 2048 + (size_t)blockIdx.x * 128 + tc * 8;
#pragma unroll
        for (int j = 0; j < 8; j++) {
            float v = acc[i][j];
            if (epi) v = v / (1.f + expf(-v));   // silu
            cp[j] = v;
        }
    }
}

// ---------------------------------------------------------------------------
// WKV5 recurrence. One block (64 threads) per (b,h). Thread j owns S[:,j].
// Chunk-stages r/k/v through smem (1 sync pair per CH steps).
// ---------------------------------------------------------------------------
#define CH 16
__global__ __launch_bounds__(64) void wkv_kernel(
    const float* __restrict__ r, const float* __restrict__ k,
    const float* __restrict__ v, const float* __restrict__ decay,
    const float* __restrict__ faaaa, float* __restrict__ y)
{
    const int bh = blockIdx.x;            // 0..255
    const int b  = bh / H_;
    const int h  = bh % H_;
    const int j  = threadIdx.x;           // 0..63

    __shared__ float rs[CH][HS_], ks[CH][HS_], vs[CH][HS_];
    __shared__ float ws[HS_], us[HS_];

    ws[j] = expf(-expf(decay[h * HS_ + j]));
    us[j] = faaaa[h * HS_ + j];

    float S[HS_];
#pragma unroll
    for (int i = 0; i < HS_; i++) S[i] = 0.f;

    const size_t base = (size_t)b * T_ * C_ + h * HS_;

    for (int t0 = 0; t0 < T_; t0 += CH) {
        __syncthreads();                  // protect smem reuse (also covers ws/us init)
#pragma unroll
        for (int s = 0; s < CH; s++) {
            size_t off = base + (size_t)(t0 + s) * C_ + j;
            rs[s][j] = r[off];
            ks[s][j] = k[off];
            vs[s][j] = v[off];
        }
        __syncthreads();

        for (int s = 0; s < CH; s++) {
            float vj = vs[s][j];
            float yy = 0.f;
#pragma unroll
            for (int i = 0; i < HS_; i++) {
                float kv = ks[s][i] * vj;
                yy = fmaf(rs[s][i], fmaf(us[i], kv, S[i]), yy);
                S[i] = fmaf(ws[i], S[i], kv);
            }
            y[base + (size_t)(t0 + s) * C_ + j] = yy;
        }
    }
}
#undef CH

// ---------------------------------------------------------------------------
// GroupNorm over each head (÷8, mean/var over 64, scale ln_w/ln_b) * gate g.
// One warp per (b,t,h); lane covers 2 elements.
// ---------------------------------------------------------------------------
__global__ __launch_bounds__(256) void gnorm_kernel(
    const float* __restrict__ y, const float* __restrict__ g,
    const float* __restrict__ lnw, const float* __restrict__ lnb,
    float* __restrict__ z)
{
    int warp = blockIdx.x * 8 + (threadIdx.x >> 5);   // over M_*H_
    int lane = threadIdx.x & 31;
    int row  = warp / H_;
    int h    = warp % H_;

    const size_t o0 = (size_t)row * C_ + h * HS_ + lane;
    float a0 = y[o0]      * 0.125f;
    float a1 = y[o0 + 32] * 0.125f;

    float s = a0 + a1;
#pragma unroll
    for (int o = 16; o; o >>= 1) s += __shfl_xor_sync(0xffffffffu, s, o);
    float mean = s * (1.f / 64.f);

    float d0 = a0 - mean, d1 = a1 - mean;
    float q = d0 * d0 + d1 * d1;
#pragma unroll
    for (int o = 16; o; o >>= 1) q += __shfl_xor_sync(0xffffffffu, q, o);
    float inv = rsqrtf(q * (1.f / 64.f) + 1e-5f);

    int c = h * HS_ + lane;
    z[o0]      = fmaf(d0 * inv, lnw[c],      lnb[c])      * g[o0];
    z[o0 + 32] = fmaf(d1 * inv, lnw[c + 32], lnb[c + 32]) * g[o0 + 32];
}

// ---------------------------------------------------------------------------
extern "C" void kernel_launch(void* const* d_in, const int* in_sizes, int n_in,
                              void* d_out, int out_size)
{
    const float* x   = (const float*)d_in[0];
    const float* tmk = (const float*)d_in[1];
    const float* tmv = (const float*)d_in[2];
    const float* tmr = (const float*)d_in[3];
    const float* tmg = (const float*)d_in[4];
    const float* dec = (const float*)d_in[5];
    const float* faa = (const float*)d_in[6];
    const float* Wr  = (const float*)d_in[7];
    const float* Wk  = (const float*)d_in[8];
    const float* Wv  = (const float*)d_in[9];
    const float* Wg  = (const float*)d_in[10];
    const float* Wo  = (const float*)d_in[11];
    const float* lnw = (const float*)d_in[12];
    const float* lnb = (const float*)d_in[13];
    float* out = (float*)d_out;

    float* sc = nullptr;
    cudaGetSymbolAddress((void**)&sc, g_scratch);   // host-side query; capture-safe

    const size_t NB = (size_t)M_ * C_;
    float* xrb = sc + 0 * NB;
    float* xkb = sc + 1 * NB;
    float* xvb = sc + 2 * NB;
    float* xgb = sc + 3 * NB;
    float* rb  = sc + 4 * NB;
    float* kb  = sc + 5 * NB;
    float* vb  = sc + 6 * NB;
    float* gb  = sc + 7 * NB;
    float* yb  = xrb;   // xr dead after r-GEMM
    float* zb  = xkb;   // xk dead after k-GEMM

    mix_kernel<<<32768, 256>>>(x, tmk, tmv, tmr, tmg, xkb, xvb, xrb, xgb);

    dim3 grid(16, 128);   // (N/128, M/128)
    sgemm_kernel<<<grid, 256>>>(xrb, Wr, rb, 0);
    sgemm_kernel<<<grid, 256>>>(xkb, Wk, kb, 0);
    sgemm_kernel<<<grid, 256>>>(xvb, Wv, vb, 0);
    sgemm_kernel<<<grid, 256>>>(xgb, Wg, gb, 1);   // silu

    wkv_kernel<<<256, 64>>>(rb, kb, vb, dec, faa, yb);

    gnorm_kernel<<<65536, 256>>>(yb, gb, lnw, lnb, zb);

    sgemm_kernel<<<grid, 256>>>(zb, Wo, out, 0);
}

// round 4
// speedup vs baseline: 2.0210x; 2.0210x over previous
#include <cuda_runtime.h>
#include <cuda_bf16.h>
#include <math.h>
#include <stdint.h>

#define B_  8
#define T_  2048
#define C_  2048
#define HS_ 64
#define H_  32
#define M_  (B_*T_)   // 16384

// ---------------------------------------------------------------------------
// Static scratch: 8 bf16 activation buffers (hi/lo x 4 mixes), 10 bf16
// transposed weight buffers, 4 fp32 GEMM outputs.
// ---------------------------------------------------------------------------
#define ACT_E   ((size_t)M_ * C_)          // 33,554,432 elems
#define ACT_BB  (ACT_E * 2)                // 64 MiB per bf16 act buffer
#define W_BB    ((size_t)C_ * C_ * 2)      // 8 MiB per bf16 weight buffer
#define F32_B   (ACT_E * 4)                // 128 MiB per fp32 buffer

__device__ __align__(256) unsigned char g_scratch[8 * ACT_BB + 10 * W_BB + 4 * F32_B];

// ---------------------------------------------------------------------------
// PTX helpers (plain sm_80+ PTX — valid under compute_103)
// ---------------------------------------------------------------------------
__device__ __forceinline__ uint32_t smem_u32(const void* p) {
    uint32_t a;
    asm("{ .reg .u64 t; cvta.to.shared.u64 t, %1; cvt.u32.u64 %0, t; }" : "=r"(a) : "l"(p));
    return a;
}

__device__ __forceinline__ void cp16(uint32_t so, const void* gp) {
    asm volatile("cp.async.cg.shared.global [%0], [%1], 16;" :: "r"(so), "l"(gp));
}
#define CP_COMMIT() asm volatile("cp.async.commit_group;" ::: "memory")
#define CP_WAIT1()  asm volatile("cp.async.wait_group 1;" ::: "memory")
#define CP_WAIT0()  asm volatile("cp.async.wait_group 0;" ::: "memory")

__device__ __forceinline__ void ldsm4(uint32_t& r0, uint32_t& r1, uint32_t& r2, uint32_t& r3,
                                      uint32_t addr) {
    asm volatile("ldmatrix.sync.aligned.m8n8.x4.shared.b16 {%0,%1,%2,%3}, [%4];"
                 : "=r"(r0), "=r"(r1), "=r"(r2), "=r"(r3) : "r"(addr));
}

__device__ __forceinline__ void mma16816(float* c, const uint32_t* a, const uint32_t* b) {
    asm("mma.sync.aligned.m16n8k16.row.col.f32.bf16.bf16.f32 "
        "{%0,%1,%2,%3}, {%4,%5,%6,%7}, {%8,%9}, {%0,%1,%2,%3};"
        : "+f"(c[0]), "+f"(c[1]), "+f"(c[2]), "+f"(c[3])
        : "r"(a[0]), "r"(a[1]), "r"(a[2]), "r"(a[3]), "r"(b[0]), "r"(b[1]));
}

// ---------------------------------------------------------------------------
// Token-shift mixing fused with fp32 -> (bf16 hi, bf16 lo) split.
// ---------------------------------------------------------------------------
__device__ __forceinline__ void split_store4(__nv_bfloat16* hi, __nv_bfloat16* lo,
                                             size_t idx, float4 o) {
    __nv_bfloat16 h0 = __float2bfloat16(o.x);
    __nv_bfloat16 h1 = __float2bfloat16(o.y);
    __nv_bfloat16 h2 = __float2bfloat16(o.z);
    __nv_bfloat16 h3 = __float2bfloat16(o.w);
    __nv_bfloat162* hp = (__nv_bfloat162*)(hi + idx);
    hp[0] = __nv_bfloat162(h0, h1);
    hp[1] = __nv_bfloat162(h2, h3);
    __nv_bfloat162* lp = (__nv_bfloat162*)(lo + idx);
    lp[0] = __nv_bfloat162(__float2bfloat16(o.x - __bfloat162float(h0)),
                           __float2bfloat16(o.y - __bfloat162float(h1)));
    lp[1] = __nv_bfloat162(__float2bfloat16(o.z - __bfloat162float(h2)),
                           __float2bfloat16(o.w - __bfloat162float(h3)));
}

__global__ __launch_bounds__(256) void mix_split_kernel(
    const float* __restrict__ x,
    const float* __restrict__ tmk, const float* __restrict__ tmv,
    const float* __restrict__ tmr, const float* __restrict__ tmg,
    __nv_bfloat16* __restrict__ xkh, __nv_bfloat16* __restrict__ xkl,
    __nv_bfloat16* __restrict__ xvh, __nv_bfloat16* __restrict__ xvl,
    __nv_bfloat16* __restrict__ xrh, __nv_bfloat16* __restrict__ xrl,
    __nv_bfloat16* __restrict__ xgh, __nv_bfloat16* __restrict__ xgl)
{
    size_t idx4 = (size_t)blockIdx.x * blockDim.x + threadIdx.x;
    size_t idx  = idx4 * 4;
    int    c    = (int)(idx % C_);
    size_t m    = idx / C_;
    int    t    = (int)(m % T_);

    float4 xc = *(const float4*)(x + idx);
    float4 xp = make_float4(0.f, 0.f, 0.f, 0.f);
    if (t != 0) xp = *(const float4*)(x + idx - C_);

    float4 o;
#define DO_MIX(TM, HI, LO)                                                  \
    {                                                                       \
        float4 w4 = *(const float4*)((TM) + c);                             \
        o.x = fmaf(w4.x, xc.x - xp.x, xp.x);                                \
        o.y = fmaf(w4.y, xc.y - xp.y, xp.y);                                \
        o.z = fmaf(w4.z, xc.z - xp.z, xp.z);                                \
        o.w = fmaf(w4.w, xc.w - xp.w, xp.w);                                \
        split_store4(HI, LO, idx, o);                                       \
    }
    DO_MIX(tmk, xkh, xkl)
    DO_MIX(tmv, xvh, xvl)
    DO_MIX(tmr, xrh, xrl)
    DO_MIX(tmg, xgh, xgl)
#undef DO_MIX
}

// ---------------------------------------------------------------------------
// Weight transpose + split: W[K,N] fp32 -> Wt_hi/Wt_lo [N,K] bf16.
// ---------------------------------------------------------------------------
__global__ __launch_bounds__(256) void wsplit_kernel(
    const float* __restrict__ W,
    __nv_bfloat16* __restrict__ hi, __nv_bfloat16* __restrict__ lo)
{
    __shared__ float tile[32][33];
    int tx = threadIdx.x, ty = threadIdx.y;
    int n0 = blockIdx.x * 32, k0 = blockIdx.y * 32;
#pragma unroll
    for (int r = ty; r < 32; r += 8)
        tile[r][tx] = W[(size_t)(k0 + r) * C_ + n0 + tx];
    __syncthreads();
#pragma unroll
    for (int r = ty; r < 32; r += 8) {
        float v = tile[tx][r];                 // = W[k0+tx][n0+r]
        __nv_bfloat16 h = __float2bfloat16(v);
        size_t o = (size_t)(n0 + r) * C_ + k0 + tx;
        hi[o] = h;
        lo[o] = __float2bfloat16(v - __bfloat162float(h));
    }
}

// ---------------------------------------------------------------------------
// bf16x3 GEMM via mma.sync.m16n8k16:
//   C[M,2048] = A[M,2048] @ Bt[2048,2048]^T   (fp32 via hi/lo split, 3 products)
// CTA tile 128x128, BK=32, 3-stage cp.async pipeline, 8 warps of 64x32.
// Smem rows padded to 80B (conflict-free ldmatrix).
// ---------------------------------------------------------------------------
#define BM 128
#define BN 128
#define BK 32
#define NCHUNK (2048 / BK)          // 64
#define ROWB 80u                    // bytes per padded smem row (32 bf16 -> 80B)
#define MAT_BYTES (128u * ROWB)     // 10240
#define STAGE_BYTES (4u * MAT_BYTES)  // 40960: Ah, Al, Bh, Bl
#define NSTAGE 3
#define GEMM_SMEM (NSTAGE * STAGE_BYTES)   // 122880
#define OFF_AH 0u
#define OFF_AL (1u * MAT_BYTES)
#define OFF_BH (2u * MAT_BYTES)
#define OFF_BL (3u * MAT_BYTES)

__device__ __forceinline__ void load_stage(
    uint32_t sstage, int k0, int tid, int m0, int n0,
    const __nv_bfloat16* Ah, const __nv_bfloat16* Al,
    const __nv_bfloat16* Bh, const __nv_bfloat16* Bl)
{
#pragma unroll
    for (int j = 0; j < 8; j++) {
        int id  = tid + 256 * j;        // 0..2047
        int sel = id >> 9;              // 0=Ah 1=Al 2=Bh 3=Bl
        int cc  = id & 511;
        int row = cc >> 2, ch = cc & 3;
        const __nv_bfloat16* base = (sel == 0) ? Ah : (sel == 1) ? Al : (sel == 2) ? Bh : Bl;
        int grow = ((sel < 2) ? m0 : n0) + row;
        const void* gp = base + (size_t)grow * 2048 + k0 + ch * 8;
        uint32_t so = sstage + (uint32_t)sel * MAT_BYTES + (uint32_t)row * ROWB + (uint32_t)ch * 16u;
        cp16(so, gp);
    }
    CP_COMMIT();
}

__global__ __launch_bounds__(256, 1) void gemm_bf16x3(
    const __nv_bfloat16* __restrict__ Ah, const __nv_bfloat16* __restrict__ Al,
    const __nv_bfloat16* __restrict__ Bh, const __nv_bfloat16* __restrict__ Bl,
    float* __restrict__ Cm, int epi)
{
    extern __shared__ __align__(128) unsigned char dsm[];
    const uint32_t sb = smem_u32(dsm);

    const int tid  = threadIdx.x;
    const int wid  = tid >> 5;
    const int lane = tid & 31;
    const int wm   = wid >> 2;          // 0..1 -> warp M origin wm*64
    const int wn   = wid & 3;           // 0..3 -> warp N origin wn*32
    const int m0   = blockIdx.y * BM;
    const int n0   = blockIdx.x * BN;

    float acc[4][4][4];
#pragma unroll
    for (int i = 0; i < 4; i++)
#pragma unroll
        for (int j = 0; j < 4; j++)
#pragma unroll
            for (int q = 0; q < 4; q++) acc[i][j][q] = 0.f;

    // ldmatrix lane addressing (within warp), computed once:
    // A: lanes 0-7 m0-7/klo, 8-15 m8-15/klo, 16-23 m0-7/khi, 24-31 m8-15/khi
    const int a_r  = (lane & 15);            // row within 16-row frag
    const int a_kb = (lane >> 4) * 16;       // 0 or 16 bytes (k half)
    // B: lanes 0-7 n0-7/klo, 8-15 n0-7/khi, 16-23 n8-15/klo, 24-31 n8-15/khi
    const int b_r  = (lane & 7) + ((lane >> 4) * 8);
    const int b_kb = ((lane >> 3) & 1) * 16;

    load_stage(sb + 0 * STAGE_BYTES, 0,  tid, m0, n0, Ah, Al, Bh, Bl);
    load_stage(sb + 1 * STAGE_BYTES, BK, tid, m0, n0, Ah, Al, Bh, Bl);

    for (int i = 0; i < NCHUNK; i++) {
        const int s = i % NSTAGE;
        const uint32_t st = sb + (uint32_t)s * STAGE_BYTES;
        CP_WAIT1();
        __syncthreads();

#pragma unroll
        for (int ks = 0; ks < 2; ks++) {
            uint32_t ah[4][4], al[4][4], bh[4][2], bl[4][2];
#pragma unroll
            for (int mi = 0; mi < 4; mi++) {
                uint32_t arow = (uint32_t)(wm * 64 + mi * 16 + a_r);
                uint32_t ao = arow * ROWB + (uint32_t)(ks * 32 + a_kb);
                ldsm4(ah[mi][0], ah[mi][1], ah[mi][2], ah[mi][3], st + OFF_AH + ao);
                ldsm4(al[mi][0], al[mi][1], al[mi][2], al[mi][3], st + OFF_AL + ao);
            }
#pragma unroll
            for (int bi = 0; bi < 2; bi++) {
                uint32_t brow = (uint32_t)(wn * 32 + bi * 16 + b_r);
                uint32_t bo = brow * ROWB + (uint32_t)(ks * 32 + b_kb);
                uint32_t t0, t1, t2, t3;
                ldsm4(t0, t1, t2, t3, st + OFF_BH + bo);
                bh[bi * 2][0] = t0; bh[bi * 2][1] = t1;
                bh[bi * 2 + 1][0] = t2; bh[bi * 2 + 1][1] = t3;
                ldsm4(t0, t1, t2, t3, st + OFF_BL + bo);
                bl[bi * 2][0] = t0; bl[bi * 2][1] = t1;
                bl[bi * 2 + 1][0] = t2; bl[bi * 2 + 1][1] = t3;
            }
#pragma unroll
            for (int mi = 0; mi < 4; mi++)
#pragma unroll
                for (int ng = 0; ng < 4; ng++) {
                    mma16816(acc[mi][ng], ah[mi], bh[ng]);
                    mma16816(acc[mi][ng], ah[mi], bl[ng]);
                    mma16816(acc[mi][ng], al[mi], bh[ng]);
                }
        }

        __syncthreads();
        if (i + 2 < NCHUNK)
            load_stage(sb + (uint32_t)((i + 2) % NSTAGE) * STAGE_BYTES,
                       (i + 2) * BK, tid, m0, n0, Ah, Al, Bh, Bl);
    }
    CP_WAIT0();

    // epilogue
#pragma unroll
    for (int mi = 0; mi < 4; mi++) {
        int row0 = m0 + wm * 64 + mi * 16 + (lane >> 2);
#pragma unroll
        for (int ng = 0; ng < 4; ng++) {
            int col = n0 + wn * 32 + ng * 8 + (lane & 3) * 2;
            float2 v0 = make_float2(acc[mi][ng][0], acc[mi][ng][1]);
            float2 v1 = make_float2(acc[mi][ng][2], acc[mi][ng][3]);
            if (epi) {
                v0.x = v0.x / (1.f + expf(-v0.x));
                v0.y = v0.y / (1.f + expf(-v0.y));
                v1.x = v1.x / (1.f + expf(-v1.x));
                v1.y = v1.y / (1.f + expf(-v1.y));
            }
            *(float2*)(Cm + (size_t)row0 * 2048 + col)       = v0;
            *(float2*)(Cm + (size_t)(row0 + 8) * 2048 + col) = v1;
        }
    }
}

// ---------------------------------------------------------------------------
// WKV5 recurrence. One block (64 threads) per (b,h). Thread j owns S[:,j].
// ---------------------------------------------------------------------------
#define CH 16
__global__ __launch_bounds__(64) void wkv_kernel(
    const float* __restrict__ r, const float* __restrict__ k,
    const float* __restrict__ v, const float* __restrict__ decay,
    const float* __restrict__ faaaa, float* __restrict__ y)
{
    const int bh = blockIdx.x;
    const int b  = bh / H_;
    const int h  = bh % H_;
    const int j  = threadIdx.x;

    __shared__ float rs[CH][HS_], ks[CH][HS_], vs[CH][HS_];
    __shared__ float ws[HS_], us[HS_];

    ws[j] = expf(-expf(decay[h * HS_ + j]));
    us[j] = faaaa[h * HS_ + j];

    float S[HS_];
#pragma unroll
    for (int i = 0; i < HS_; i++) S[i] = 0.f;

    const size_t base = (size_t)b * T_ * C_ + h * HS_;

    for (int t0 = 0; t0 < T_; t0 += CH) {
        __syncthreads();
#pragma unroll
        for (int s = 0; s < CH; s++) {
            size_t off = base + (size_t)(t0 + s) * C_ + j;
            rs[s][j] = r[off];
            ks[s][j] = k[off];
            vs[s][j] = v[off];
        }
        __syncthreads();

        for (int s = 0; s < CH; s++) {
            float vj = vs[s][j];
            float yy = 0.f;
#pragma unroll
            for (int i = 0; i < HS_; i++) {
                float kv = ks[s][i] * vj;
                yy = fmaf(rs[s][i], fmaf(us[i], kv, S[i]), yy);
                S[i] = fmaf(ws[i], S[i], kv);
            }
            y[base + (size_t)(t0 + s) * C_ + j] = yy;
        }
    }
}
#undef CH

// ---------------------------------------------------------------------------
// GroupNorm (/8, per head) * gate, output split to bf16 hi/lo for Wo GEMM.
// ---------------------------------------------------------------------------
__global__ __launch_bounds__(256) void gnorm_kernel(
    const float* __restrict__ y, const float* __restrict__ g,
    const float* __restrict__ lnw, const float* __restrict__ lnb,
    __nv_bfloat16* __restrict__ zh, __nv_bfloat16* __restrict__ zl)
{
    int warp = blockIdx.x * 8 + (threadIdx.x >> 5);
    int lane = threadIdx.x & 31;
    int row  = warp / H_;
    int h    = warp % H_;

    const size_t o0 = (size_t)row * C_ + h * HS_ + lane;
    float a0 = y[o0]      * 0.125f;
    float a1 = y[o0 + 32] * 0.125f;

    float s = a0 + a1;
#pragma unroll
    for (int o = 16; o; o >>= 1) s += __shfl_xor_sync(0xffffffffu, s, o);
    float mean = s * (1.f / 64.f);

    float d0 = a0 - mean, d1 = a1 - mean;
    float q = d0 * d0 + d1 * d1;
#pragma unroll
    for (int o = 16; o; o >>= 1) q += __shfl_xor_sync(0xffffffffu, q, o);
    float inv = rsqrtf(q * (1.f / 64.f) + 1e-5f);

    int c = h * HS_ + lane;
    float z0 = fmaf(d0 * inv, lnw[c],      lnb[c])      * g[o0];
    float z1 = fmaf(d1 * inv, lnw[c + 32], lnb[c + 32]) * g[o0 + 32];

    __nv_bfloat16 h0 = __float2bfloat16(z0);
    __nv_bfloat16 h1 = __float2bfloat16(z1);
    zh[o0]      = h0;
    zh[o0 + 32] = h1;
    zl[o0]      = __float2bfloat16(z0 - __bfloat162float(h0));
    zl[o0 + 32] = __float2bfloat16(z1 - __bfloat162float(h1));
}

// ---------------------------------------------------------------------------
extern "C" void kernel_launch(void* const* d_in, const int* in_sizes, int n_in,
                              void* d_out, int out_size)
{
    const float* x   = (const float*)d_in[0];
    const float* tmk = (const float*)d_in[1];
    const float* tmv = (const float*)d_in[2];
    const float* tmr = (const float*)d_in[3];
    const float* tmg = (const float*)d_in[4];
    const float* dec = (const float*)d_in[5];
    const float* faa = (const float*)d_in[6];
    const float* Wr  = (const float*)d_in[7];
    const float* Wk  = (const float*)d_in[8];
    const float* Wv  = (const float*)d_in[9];
    const float* Wg  = (const float*)d_in[10];
    const float* Wo  = (const float*)d_in[11];
    const float* lnw = (const float*)d_in[12];
    const float* lnb = (const float*)d_in[13];
    float* out = (float*)d_out;

    unsigned char* sc = nullptr;
    cudaGetSymbolAddress((void**)&sc, g_scratch);

    __nv_bfloat16* act[8];   // xr_hi, xr_lo, xk_hi, xk_lo, xv_hi, xv_lo, xg_hi, xg_lo
    for (int i = 0; i < 8; i++) act[i] = (__nv_bfloat16*)(sc + (size_t)i * ACT_BB);
    __nv_bfloat16* wt[10];   // wr, wk, wv, wg, wo (hi/lo pairs)
    for (int i = 0; i < 10; i++) wt[i] = (__nv_bfloat16*)(sc + 8 * ACT_BB + (size_t)i * W_BB);
    float* f32b = (float*)(sc + 8 * ACT_BB + 10 * W_BB);
    float* rb = f32b + 0 * ACT_E;
    float* kb = f32b + 1 * ACT_E;
    float* vb = f32b + 2 * ACT_E;
    float* gb = f32b + 3 * ACT_E;
    float* yb = (float*)act[2];          // aliases xk hi+lo (dead after k GEMM)
    __nv_bfloat16* zh = act[4];          // aliases xv_hi (dead after v GEMM)
    __nv_bfloat16* zl = act[5];          // aliases xv_lo

    cudaFuncSetAttribute(gemm_bf16x3, cudaFuncAttributeMaxDynamicSharedMemorySize, GEMM_SMEM);

    mix_split_kernel<<<32768, 256>>>(x, tmk, tmv, tmr, tmg,
                                     act[2], act[3], act[4], act[5],
                                     act[0], act[1], act[6], act[7]);

    dim3 wgrid(64, 64);
    dim3 wblk(32, 8);
    wsplit_kernel<<<wgrid, wblk>>>(Wr, wt[0], wt[1]);
    wsplit_kernel<<<wgrid, wblk>>>(Wk, wt[2], wt[3]);
    wsplit_kernel<<<wgrid, wblk>>>(Wv, wt[4], wt[5]);
    wsplit_kernel<<<wgrid, wblk>>>(Wg, wt[6], wt[7]);
    wsplit_kernel<<<wgrid, wblk>>>(Wo, wt[8], wt[9]);

    dim3 ggrid(C_ / BN, M_ / BM);   // (16, 128)
    gemm_bf16x3<<<ggrid, 256, GEMM_SMEM>>>(act[0], act[1], wt[0], wt[1], rb, 0);
    gemm_bf16x3<<<ggrid, 256, GEMM_SMEM>>>(act[2], act[3], wt[2], wt[3], kb, 0);
    gemm_bf16x3<<<ggrid, 256, GEMM_SMEM>>>(act[4], act[5], wt[4], wt[5], vb, 0);
    gemm_bf16x3<<<ggrid, 256, GEMM_SMEM>>>(act[6], act[7], wt[6], wt[7], gb, 1);

    wkv_kernel<<<256, 64>>>(rb, kb, vb, dec, faa, yb);

    gnorm_kernel<<<65536, 256>>>(yb, gb, lnw, lnb, zh, zl);

    gemm_bf16x3<<<ggrid, 256, GEMM_SMEM>>>(zh, zl, wt[8], wt[9], out, 0);
}

// round 5
// speedup vs baseline: 2.1222x; 1.0501x over previous
#include <cuda_runtime.h>
#include <cuda_bf16.h>
#include <math.h>
#include <stdint.h>

#define B_  8
#define T_  2048
#define C_  2048
#define HS_ 64
#define H_  32
#define M_  (B_*T_)   // 16384

// ---------------------------------------------------------------------------
// Static scratch
// ---------------------------------------------------------------------------
#define ACT_E   ((size_t)M_ * C_)          // 33,554,432 elems
#define ACT_BB  (ACT_E * 2)                // 64 MiB per bf16 act buffer
#define W_E     ((size_t)C_ * C_)
#define W_BB    (W_E * 2)                  // 8 MiB per bf16 weight buffer
#define F32_B   (ACT_E * 4)                // 128 MiB per fp32 buffer

__device__ __align__(256) unsigned char g_scratch[8 * ACT_BB + 10 * W_BB + 4 * F32_B];

// ---------------------------------------------------------------------------
// PTX helpers (plain sm_80+ PTX — valid under compute_103)
// ---------------------------------------------------------------------------
__device__ __forceinline__ uint32_t smem_u32(const void* p) {
    uint32_t a;
    asm("{ .reg .u64 t; cvta.to.shared.u64 t, %1; cvt.u32.u64 %0, t; }" : "=r"(a) : "l"(p));
    return a;
}

__device__ __forceinline__ void cp16(uint32_t so, const void* gp) {
    asm volatile("cp.async.cg.shared.global [%0], [%1], 16;" :: "r"(so), "l"(gp));
}
#define CP_COMMIT() asm volatile("cp.async.commit_group;" ::: "memory")
#define CP_WAIT2()  asm volatile("cp.async.wait_group 2;" ::: "memory")
#define CP_WAIT0()  asm volatile("cp.async.wait_group 0;" ::: "memory")

__device__ __forceinline__ void ldsm4(uint32_t& r0, uint32_t& r1, uint32_t& r2, uint32_t& r3,
                                      uint32_t addr) {
    asm volatile("ldmatrix.sync.aligned.m8n8.x4.shared.b16 {%0,%1,%2,%3}, [%4];"
                 : "=r"(r0), "=r"(r1), "=r"(r2), "=r"(r3) : "r"(addr));
}

__device__ __forceinline__ void mma16816(float* c, const uint32_t* a, const uint32_t* b) {
    asm("mma.sync.aligned.m16n8k16.row.col.f32.bf16.bf16.f32 "
        "{%0,%1,%2,%3}, {%4,%5,%6,%7}, {%8,%9}, {%0,%1,%2,%3};"
        : "+f"(c[0]), "+f"(c[1]), "+f"(c[2]), "+f"(c[3])
        : "r"(a[0]), "r"(a[1]), "r"(a[2]), "r"(a[3]), "r"(b[0]), "r"(b[1]));
}

// ---------------------------------------------------------------------------
// Fused weight transpose + split (all 5 weights, blockIdx.z selects).
// W[K,N] fp32 -> Wt_hi/Wt_lo [N,K] bf16.
// ---------------------------------------------------------------------------
__global__ __launch_bounds__(256) void wsplit_all_kernel(
    const float* __restrict__ W0, const float* __restrict__ W1,
    const float* __restrict__ W2, const float* __restrict__ W3,
    const float* __restrict__ W4,
    __nv_bfloat16* __restrict__ wtbase)
{
    __shared__ float tile[32][33];
    const float* Ws[5] = {W0, W1, W2, W3, W4};
    const float* W = Ws[blockIdx.z];
    __nv_bfloat16* hi = wtbase + (size_t)(2 * blockIdx.z)     * W_E;
    __nv_bfloat16* lo = wtbase + (size_t)(2 * blockIdx.z + 1) * W_E;

    int tx = threadIdx.x, ty = threadIdx.y;
    int n0 = blockIdx.x * 32, k0 = blockIdx.y * 32;
#pragma unroll
    for (int r = ty; r < 32; r += 8)
        tile[r][tx] = W[(size_t)(k0 + r) * C_ + n0 + tx];
    __syncthreads();
#pragma unroll
    for (int r = ty; r < 32; r += 8) {
        float v = tile[tx][r];                 // = W[k0+tx][n0+r]
        __nv_bfloat16 h = __float2bfloat16(v);
        size_t o = (size_t)(n0 + r) * C_ + k0 + tx;
        hi[o] = h;
        lo[o] = __float2bfloat16(v - __bfloat162float(h));
    }
}

// ---------------------------------------------------------------------------
// Token-shift mixing fused with fp32 -> (bf16 hi, bf16 lo) split.
// ---------------------------------------------------------------------------
__device__ __forceinline__ void split_store4(__nv_bfloat16* hi, __nv_bfloat16* lo,
                                             size_t idx, float4 o) {
    __nv_bfloat16 h0 = __float2bfloat16(o.x);
    __nv_bfloat16 h1 = __float2bfloat16(o.y);
    __nv_bfloat16 h2 = __float2bfloat16(o.z);
    __nv_bfloat16 h3 = __float2bfloat16(o.w);
    __nv_bfloat162* hp = (__nv_bfloat162*)(hi + idx);
    hp[0] = __nv_bfloat162(h0, h1);
    hp[1] = __nv_bfloat162(h2, h3);
    __nv_bfloat162* lp = (__nv_bfloat162*)(lo + idx);
    lp[0] = __nv_bfloat162(__float2bfloat16(o.x - __bfloat162float(h0)),
                           __float2bfloat16(o.y - __bfloat162float(h1)));
    lp[1] = __nv_bfloat162(__float2bfloat16(o.z - __bfloat162float(h2)),
                           __float2bfloat16(o.w - __bfloat162float(h3)));
}

__global__ __launch_bounds__(256) void mix_split_kernel(
    const float* __restrict__ x,
    const float* __restrict__ tmk, const float* __restrict__ tmv,
    const float* __restrict__ tmr, const float* __restrict__ tmg,
    __nv_bfloat16* __restrict__ xkh, __nv_bfloat16* __restrict__ xkl,
    __nv_bfloat16* __restrict__ xvh, __nv_bfloat16* __restrict__ xvl,
    __nv_bfloat16* __restrict__ xrh, __nv_bfloat16* __restrict__ xrl,
    __nv_bfloat16* __restrict__ xgh, __nv_bfloat16* __restrict__ xgl)
{
    size_t idx4 = (size_t)blockIdx.x * blockDim.x + threadIdx.x;
    size_t idx  = idx4 * 4;
    int    c    = (int)(idx % C_);
    size_t m    = idx / C_;
    int    t    = (int)(m % T_);

    float4 xc = *(const float4*)(x + idx);
    float4 xp = make_float4(0.f, 0.f, 0.f, 0.f);
    if (t != 0) xp = *(const float4*)(x + idx - C_);

    float4 o;
#define DO_MIX(TM, HI, LO)                                                  \
    {                                                                       \
        float4 w4 = *(const float4*)((TM) + c);                             \
        o.x = fmaf(w4.x, xc.x - xp.x, xp.x);                                \
        o.y = fmaf(w4.y, xc.y - xp.y, xp.y);                                \
        o.z = fmaf(w4.z, xc.z - xp.z, xp.z);                                \
        o.w = fmaf(w4.w, xc.w - xp.w, xp.w);                                \
        split_store4(HI, LO, idx, o);                                       \
    }
    DO_MIX(tmk, xkh, xkl)
    DO_MIX(tmv, xvh, xvl)
    DO_MIX(tmr, xrh, xrl)
    DO_MIX(tmg, xgh, xgl)
#undef DO_MIX
}

// ---------------------------------------------------------------------------
// bf16x3 GEMM via mma.sync.m16n8k16:
//   C[M,2048] = A[M,2048] @ Bt[2048,2048]^T  (fp32 via hi/lo split, 3 products)
// CTA tile 128x128, BK=32, 4-stage cp.async pipeline, ONE sync per chunk,
// 8 warps of 64x32. Smem rows padded to 80B (conflict-free ldmatrix).
// ---------------------------------------------------------------------------
#define BM 128
#define BN 128
#define BK 32
#define NCHUNK (2048 / BK)          // 64
#define ROWB 80u                    // bytes per padded smem row (32 bf16 -> 80B)
#define MAT_BYTES (128u * ROWB)     // 10240
#define STAGE_BYTES (4u * MAT_BYTES)  // 40960: Ah, Al, Bh, Bl
#define NSTAGE 4
#define GEMM_SMEM (NSTAGE * STAGE_BYTES)   // 163840
#define OFF_AH 0u
#define OFF_AL (1u * MAT_BYTES)
#define OFF_BH (2u * MAT_BYTES)
#define OFF_BL (3u * MAT_BYTES)

__device__ __forceinline__ void load_stage(
    uint32_t sstage, int k0, int tid, int m0, int n0,
    const __nv_bfloat16* Ah, const __nv_bfloat16* Al,
    const __nv_bfloat16* Bh, const __nv_bfloat16* Bl)
{
#pragma unroll
    for (int j = 0; j < 8; j++) {
        int id  = tid + 256 * j;        // 0..2047
        int sel = id >> 9;              // 0=Ah 1=Al 2=Bh 3=Bl
        int cc  = id & 511;
        int row = cc >> 2, ch = cc & 3;
        const __nv_bfloat16* base = (sel == 0) ? Ah : (sel == 1) ? Al : (sel == 2) ? Bh : Bl;
        int grow = ((sel < 2) ? m0 : n0) + row;
        const void* gp = base + (size_t)grow * 2048 + k0 + ch * 8;
        uint32_t so = sstage + (uint32_t)sel * MAT_BYTES + (uint32_t)row * ROWB + (uint32_t)ch * 16u;
        cp16(so, gp);
    }
    CP_COMMIT();
}

__global__ __launch_bounds__(256, 1) void gemm_bf16x3(
    const __nv_bfloat16* __restrict__ Ah, const __nv_bfloat16* __restrict__ Al,
    const __nv_bfloat16* __restrict__ Bh, const __nv_bfloat16* __restrict__ Bl,
    float* __restrict__ Cm, int epi)
{
    extern __shared__ __align__(128) unsigned char dsm[];
    const uint32_t sb = smem_u32(dsm);

    const int tid  = threadIdx.x;
    const int wid  = tid >> 5;
    const int lane = tid & 31;
    const int wm   = wid >> 2;          // 0..1 -> warp M origin wm*64
    const int wn   = wid & 3;           // 0..3 -> warp N origin wn*32
    const int m0   = blockIdx.y * BM;
    const int n0   = blockIdx.x * BN;

    float acc[4][4][4];
#pragma unroll
    for (int i = 0; i < 4; i++)
#pragma unroll
        for (int j = 0; j < 4; j++)
#pragma unroll
            for (int q = 0; q < 4; q++) acc[i][j][q] = 0.f;

    const int a_r  = (lane & 15);
    const int a_kb = (lane >> 4) * 16;
    const int b_r  = (lane & 7) + ((lane >> 4) * 8);
    const int b_kb = ((lane >> 3) & 1) * 16;

    // prologue: fill 3 of 4 stages
    load_stage(sb + 0 * STAGE_BYTES, 0 * BK, tid, m0, n0, Ah, Al, Bh, Bl);
    load_stage(sb + 1 * STAGE_BYTES, 1 * BK, tid, m0, n0, Ah, Al, Bh, Bl);
    load_stage(sb + 2 * STAGE_BYTES, 2 * BK, tid, m0, n0, Ah, Al, Bh, Bl);

    for (int i = 0; i < NCHUNK; i++) {
        const uint32_t st = sb + (uint32_t)(i & 3) * STAGE_BYTES;
        CP_WAIT2();               // stage i guaranteed complete
        __syncthreads();          // all warps done reading slot (i+3)&3 (== stage i-1)

        if (i + 3 < NCHUNK)
            load_stage(sb + (uint32_t)((i + 3) & 3) * STAGE_BYTES,
                       (i + 3) * BK, tid, m0, n0, Ah, Al, Bh, Bl);
        else
            CP_COMMIT();          // empty group keeps wait_group accounting uniform

#pragma unroll
        for (int ks = 0; ks < 2; ks++) {
            uint32_t ah[4][4], al[4][4], bh[4][2], bl[4][2];
#pragma unroll
            for (int mi = 0; mi < 4; mi++) {
                uint32_t arow = (uint32_t)(wm * 64 + mi * 16 + a_r);
                uint32_t ao = arow * ROWB + (uint32_t)(ks * 32 + a_kb);
                ldsm4(ah[mi][0], ah[mi][1], ah[mi][2], ah[mi][3], st + OFF_AH + ao);
                ldsm4(al[mi][0], al[mi][1], al[mi][2], al[mi][3], st + OFF_AL + ao);
            }
#pragma unroll
            for (int bi = 0; bi < 2; bi++) {
                uint32_t brow = (uint32_t)(wn * 32 + bi * 16 + b_r);
                uint32_t bo = brow * ROWB + (uint32_t)(ks * 32 + b_kb);
                uint32_t t0, t1, t2, t3;
                ldsm4(t0, t1, t2, t3, st + OFF_BH + bo);
                bh[bi * 2][0] = t0; bh[bi * 2][1] = t1;
                bh[bi * 2 + 1][0] = t2; bh[bi * 2 + 1][1] = t3;
                ldsm4(t0, t1, t2, t3, st + OFF_BL + bo);
                bl[bi * 2][0] = t0; bl[bi * 2][1] = t1;
                bl[bi * 2 + 1][0] = t2; bl[bi * 2 + 1][1] = t3;
            }
#pragma unroll
            for (int mi = 0; mi < 4; mi++)
#pragma unroll
                for (int ng = 0; ng < 4; ng++) {
                    mma16816(acc[mi][ng], ah[mi], bh[ng]);
                    mma16816(acc[mi][ng], ah[mi], bl[ng]);
                    mma16816(acc[mi][ng], al[mi], bh[ng]);
                }
        }
    }
    CP_WAIT0();

    // epilogue
#pragma unroll
    for (int mi = 0; mi < 4; mi++) {
        int row0 = m0 + wm * 64 + mi * 16 + (lane >> 2);
#pragma unroll
        for (int ng = 0; ng < 4; ng++) {
            int col = n0 + wn * 32 + ng * 8 + (lane & 3) * 2;
            float2 v0 = make_float2(acc[mi][ng][0], acc[mi][ng][1]);
            float2 v1 = make_float2(acc[mi][ng][2], acc[mi][ng][3]);
            if (epi) {
                v0.x = v0.x / (1.f + expf(-v0.x));
                v0.y = v0.y / (1.f + expf(-v0.y));
                v1.x = v1.x / (1.f + expf(-v1.x));
                v1.y = v1.y / (1.f + expf(-v1.y));
            }
            *(float2*)(Cm + (size_t)row0 * 2048 + col)       = v0;
            *(float2*)(Cm + (size_t)(row0 + 8) * 2048 + col) = v1;
        }
    }
}

// ---------------------------------------------------------------------------
// WKV5 recurrence. One block (64 threads) per (b,h). Thread j owns S[:,j].
// Optimization: y_j(t) = sum_i r_i*S_ij + v_j * c_t, c_t = sum_i r_i*u_i*k_i,
// with c_t hoisted (computed once per chunk, shared across all j).
// ---------------------------------------------------------------------------
#define CH 16
__global__ __launch_bounds__(64) void wkv_kernel(
    const float* __restrict__ r, const float* __restrict__ k,
    const float* __restrict__ v, const float* __restrict__ decay,
    const float* __restrict__ faaaa, float* __restrict__ y)
{
    const int bh = blockIdx.x;
    const int b  = bh / H_;
    const int h  = bh % H_;
    const int j  = threadIdx.x;

    __shared__ float rs[CH][HS_], ks[CH][HS_], vs[CH][HS_], cs[CH];
    __shared__ float ws[HS_], us[HS_];

    ws[j] = expf(-expf(decay[h * HS_ + j]));
    us[j] = faaaa[h * HS_ + j];

    float S[HS_];
#pragma unroll
    for (int i = 0; i < HS_; i++) S[i] = 0.f;

    const size_t base = (size_t)b * T_ * C_ + h * HS_;

    for (int t0 = 0; t0 < T_; t0 += CH) {
        __syncthreads();
#pragma unroll
        for (int s = 0; s < CH; s++) {
            size_t off = base + (size_t)(t0 + s) * C_ + j;
            rs[s][j] = r[off];
            ks[s][j] = k[off];
            vs[s][j] = v[off];
        }
        __syncthreads();
        if (j < CH) {
            float c = 0.f;
#pragma unroll
            for (int i = 0; i < HS_; i++)
                c = fmaf(rs[j][i] * us[i], ks[j][i], c);
            cs[j] = c;
        }
        __syncthreads();

        for (int s = 0; s < CH; s++) {
            float vj = vs[s][j];
            float yy = cs[s] * vj;
#pragma unroll
            for (int i = 0; i < HS_; i++) {
                yy = fmaf(rs[s][i], S[i], yy);          // uses S before update
                float kv = ks[s][i] * vj;
                S[i] = fmaf(ws[i], S[i], kv);
            }
            y[base + (size_t)(t0 + s) * C_ + j] = yy;
        }
    }
}
#undef CH

// ---------------------------------------------------------------------------
// GroupNorm (/8, per head) * gate, output split to bf16 hi/lo for Wo GEMM.
// ---------------------------------------------------------------------------
__global__ __launch_bounds__(256) void gnorm_kernel(
    const float* __restrict__ y, const float* __restrict__ g,
    const float* __restrict__ lnw, const float* __restrict__ lnb,
    __nv_bfloat16* __restrict__ zh, __nv_bfloat16* __restrict__ zl)
{
    int warp = blockIdx.x * 8 + (threadIdx.x >> 5);
    int lane = threadIdx.x & 31;
    int row  = warp / H_;
    int h    = warp % H_;

    const size_t o0 = (size_t)row * C_ + h * HS_ + lane;
    float a0 = y[o0]      * 0.125f;
    float a1 = y[o0 + 32] * 0.125f;

    float s = a0 + a1;
#pragma unroll
    for (int o = 16; o; o >>= 1) s += __shfl_xor_sync(0xffffffffu, s, o);
    float mean = s * (1.f / 64.f);

    float d0 = a0 - mean, d1 = a1 - mean;
    float q = d0 * d0 + d1 * d1;
#pragma unroll
    for (int o = 16; o; o >>= 1) q += __shfl_xor_sync(0xffffffffu, q, o);
    float inv = rsqrtf(q * (1.f / 64.f) + 1e-5f);

    int c = h * HS_ + lane;
    float z0 = fmaf(d0 * inv, lnw[c],      lnb[c])      * g[o0];
    float z1 = fmaf(d1 * inv, lnw[c + 32], lnb[c + 32]) * g[o0 + 32];

    __nv_bfloat16 h0 = __float2bfloat16(z0);
    __nv_bfloat16 h1 = __float2bfloat16(z1);
    zh[o0]      = h0;
    zh[o0 + 32] = h1;
    zl[o0]      = __float2bfloat16(z0 - __bfloat162float(h0));
    zl[o0 + 32] = __float2bfloat16(z1 - __bfloat162float(h1));
}

// ---------------------------------------------------------------------------
extern "C" void kernel_launch(void* const* d_in, const int* in_sizes, int n_in,
                              void* d_out, int out_size)
{
    const float* x   = (const float*)d_in[0];
    const float* tmk = (const float*)d_in[1];
    const float* tmv = (const float*)d_in[2];
    const float* tmr = (const float*)d_in[3];
    const float* tmg = (const float*)d_in[4];
    const float* dec = (const float*)d_in[5];
    const float* faa = (const float*)d_in[6];
    const float* Wr  = (const float*)d_in[7];
    const float* Wk  = (const float*)d_in[8];
    const float* Wv  = (const float*)d_in[9];
    const float* Wg  = (const float*)d_in[10];
    const float* Wo  = (const float*)d_in[11];
    const float* lnw = (const float*)d_in[12];
    const float* lnb = (const float*)d_in[13];
    float* out = (float*)d_out;

    unsigned char* sc = nullptr;
    cudaGetSymbolAddress((void**)&sc, g_scratch);

    __nv_bfloat16* act[8];   // xr_hi, xr_lo, xk_hi, xk_lo, xv_hi, xv_lo, xg_hi, xg_lo
    for (int i = 0; i < 8; i++) act[i] = (__nv_bfloat16*)(sc + (size_t)i * ACT_BB);
    __nv_bfloat16* wtbase = (__nv_bfloat16*)(sc + 8 * ACT_BB);
    __nv_bfloat16* wt[10];   // wr, wk, wv, wg, wo (hi/lo pairs)
    for (int i = 0; i < 10; i++) wt[i] = wtbase + (size_t)i * W_E;
    float* f32b = (float*)(sc + 8 * ACT_BB + 10 * W_BB);
    float* rb = f32b + 0 * ACT_E;
    float* kb = f32b + 1 * ACT_E;
    float* vb = f32b + 2 * ACT_E;
    float* gb = f32b + 3 * ACT_E;
    float* yb = (float*)act[2];          // aliases xk hi+lo (dead after k GEMM)
    __nv_bfloat16* zh = act[4];          // aliases xv_hi (dead after v GEMM)
    __nv_bfloat16* zl = act[5];          // aliases xv_lo

    cudaFuncSetAttribute(gemm_bf16x3, cudaFuncAttributeMaxDynamicSharedMemorySize, GEMM_SMEM);

    // launch 1: fused weight split (profiler skips 5 -> 6th launch is gemm #4)
    dim3 wgrid(64, 64, 5);
    dim3 wblk(32, 8);
    wsplit_all_kernel<<<wgrid, wblk>>>(Wr, Wk, Wv, Wg, Wo, wtbase);

    // launch 2: mixing
    mix_split_kernel<<<32768, 256>>>(x, tmk, tmv, tmr, tmg,
                                     act[2], act[3], act[4], act[5],
                                     act[0], act[1], act[6], act[7]);

    // launches 3-6: projection GEMMs (launch 6 = gate GEMM gets profiled)
    dim3 ggrid(C_ / BN, M_ / BM);   // (16, 128)
    gemm_bf16x3<<<ggrid, 256, GEMM_SMEM>>>(act[0], act[1], wt[0], wt[1], rb, 0);
    gemm_bf16x3<<<ggrid, 256, GEMM_SMEM>>>(act[2], act[3], wt[2], wt[3], kb, 0);
    gemm_bf16x3<<<ggrid, 256, GEMM_SMEM>>>(act[4], act[5], wt[4], wt[5], vb, 0);
    gemm_bf16x3<<<ggrid, 256, GEMM_SMEM>>>(act[6], act[7], wt[6], wt[7], gb, 1);

    wkv_kernel<<<256, 64>>>(rb, kb, vb, dec, faa, yb);

    gnorm_kernel<<<65536, 256>>>(yb, gb, lnw, lnb, zh, zl);

    gemm_bf16x3<<<ggrid, 256, GEMM_SMEM>>>(zh, zl, wt[8], wt[9], out, 0);
}